// round 15
// baseline (speedup 1.0000x reference)
#include <cuda_runtime.h>

typedef unsigned long long ull;

// ---------------- problem constants ----------------
#define BB 8
#define S1C 256
#define M2C 129
#define PLANE (S1C*M2C)            // 33024
#define N0 (BB*32*PLANE)           // 8454144
#define N1 (BB*64*128*64)          // 4194304
#define N2 (BB*64*64*32)           // 1048576
#define OFF_SKIP0 (N0)
#define OFF_SKIP1 (2*N0)
#define OFF_SKIP2 (2*N0+N1)

// complex scratch (16B-aligned for vector access)
__device__ __align__(16) float2 g_c0[BB*32*128*64];  // x1_0 CORNERS ONLY, [b][ch][r][c] (16.8MB)
__device__ __align__(16) float2 g_x1_1[N1];
// level-0 layer-1 separable tables: pre-act = A(s1) + B(m2) + C(b)
__device__ float2 g_tabA[256*32];
__device__ float2 g_tabB[129*32];
__device__ float2 g_tabC[8*32];

// ---------------- packed f32x2 helpers ----------------
__device__ __forceinline__ ull pk(float x, float y){
    ull r; asm("mov.b64 %0, {%1,%2};" : "=l"(r) : "f"(x), "f"(y)); return r;
}
__device__ __forceinline__ void upk(ull v, float& x, float& y){
    asm("mov.b64 {%0,%1}, %2;" : "=f"(x), "=f"(y) : "l"(v));
}
__device__ __forceinline__ void ffma2(ull& d, ull a, ull b){
    asm("fma.rn.f32x2 %0, %1, %2, %0;" : "+l"(d) : "l"(a), "l"(b));
}

__device__ __forceinline__ float gelu1(float v){
    float u = 0.7978845608028654f * v * fmaf(0.044715f * v, v, 1.0f);
    float t;
    asm("tanh.approx.f32 %0, %1;" : "=f"(t) : "f"(u));
    return 0.5f * v * (1.0f + t);
}

__device__ __forceinline__ void kpow3(float kv, float* r0, float* i0,
                                      float* r1, float* i1, float* r2, float* i2){
    float a  = fabsf(kv);
    float c1 = cbrtf(a);
    float c2 = c1 * c1;
    if (kv >= 0.0f){
        *r0 = c1;        *i0 = 0.0f;
        *r1 = c2;        *i1 = 0.0f;
        *r2 = a;         *i2 = 0.0f;
    } else {
        *r0 =  0.5f*c1;  *i0 = 0.86602540f*c1;
        *r1 = -0.5f*c2;  *i1 = 0.86602540f*c2;
        *r2 = -a;        *i2 = 0.0f;
    }
}

// ---------------- K0: prep separable layer-1 tables ----------------
__global__ void k_prep(const float* __restrict__ Re,
                       const float* __restrict__ w1r, const float* __restrict__ w1i,
                       const float* __restrict__ b1r, const float* __restrict__ b1i)
{
    int idx = blockIdx.x * 256 + threadIdx.x;
    if (idx < 8192){                                    // A[s1][o]
        int s1 = idx >> 5, o = idx & 31;
        float kv = (s1 < 128) ? (float)s1 : (float)(s1 - 256);
        float f0r,f0i,f1r,f1i,f2r,f2i;
        kpow3(kv, &f0r,&f0i, &f1r,&f1i, &f2r,&f2i);
        float2 a = make_float2(0,0);
        float2 w;
        w = make_float2(w1r[o*9+0], w1i[o*9+0]); a.x += w.x*f0r - w.y*f0i; a.y += w.x*f0i + w.y*f0r;
        w = make_float2(w1r[o*9+2], w1i[o*9+2]); a.x += w.x*f1r - w.y*f1i; a.y += w.x*f1i + w.y*f1r;
        w = make_float2(w1r[o*9+4], w1i[o*9+4]); a.x += w.x*f2r - w.y*f2i; a.y += w.x*f2i + w.y*f2r;
        g_tabA[idx] = a;
    } else if (idx < 8192 + 4128){                      // B[m2][o]
        int j = idx - 8192;
        int m2 = j / 32, o = j % 32;
        float kv = (m2 < 128) ? (float)m2 : -128.0f;
        float f0r,f0i,f1r,f1i,f2r,f2i;
        kpow3(kv, &f0r,&f0i, &f1r,&f1i, &f2r,&f2i);
        float2 a = make_float2(0,0);
        float2 w;
        w = make_float2(w1r[o*9+1], w1i[o*9+1]); a.x += w.x*f0r - w.y*f0i; a.y += w.x*f0i + w.y*f0r;
        w = make_float2(w1r[o*9+3], w1i[o*9+3]); a.x += w.x*f1r - w.y*f1i; a.y += w.x*f1i + w.y*f1r;
        w = make_float2(w1r[o*9+5], w1i[o*9+5]); a.x += w.x*f2r - w.y*f2i; a.y += w.x*f2i + w.y*f2r;
        g_tabB[j] = a;
    } else if (idx < 8192 + 4128 + 256){                // C[b][o]
        int j = idx - 8192 - 4128;
        int b = j >> 5, o = j & 31;
        float r = Re[b];
        float c1 = cbrtf(r), c2 = c1*c1;
        float2 a = make_float2(b1r[o], b1i[o]);
        a.x += w1r[o*9+6]*c1; a.y += w1i[o*9+6]*c1;
        a.x += w1r[o*9+7]*c2; a.y += w1i[o*9+7]*c2;
        a.x += w1r[o*9+8]*r;  a.y += w1i[o*9+8]*r;
        g_tabC[j] = a;
    }
}

// ---------------- K1: fused level-0 (128 px/block, 2 px/thread, 8 outs) ----------------
__global__ void __launch_bounds__(256)
k_level0(const float* __restrict__ xr, const float* __restrict__ xi,
         const float* __restrict__ w2r, const float* __restrict__ w2i,
         const float* __restrict__ b2r, const float* __restrict__ b2i,
         const float* __restrict__ w0r, const float* __restrict__ w0i,
         float* __restrict__ out)
{
    __shared__ __align__(16) float2 sw2t[1024];   // w2 transposed to [i*32+o]  8KB
    __shared__ __align__(16) float2 sw0[1024];    // w0 already [i*32+o]        8KB
    __shared__ __align__(16) float2 hq[32*128];   // [ch][px] exchange          32KB

    for (int t = threadIdx.x; t < 1024; t += 256){
        int o = t >> 5, i = t & 31;
        sw2t[i*32 + o] = make_float2(w2r[t], w2i[t]);
        sw0[t]         = make_float2(w0r[t], w0i[t]);
    }

    int tid = threadIdx.x;
    int pr  = tid & 63;               // pixel-pair id
    int ob  = (tid >> 6) * 8;         // 0,8,16,24
    int p0  = blockIdx.x * 128 + 2*pr;
    int b   = p0 / PLANE;
    int sp0 = p0 - b * PLANE;
    int s1a = sp0 / M2C;
    int m2a = sp0 - s1a * M2C;
    int s1b = s1a, m2b = m2a + 1;
    if (m2b == M2C){ m2b = 0; s1b = s1a + 1; }
    int xoff = b * 32 * PLANE + sp0;  // even

    // corner membership (for compact complex store)
    bool ca = (m2a < 64) && (s1a < 64 || s1a >= 192);
    bool cb = (m2b < 64) && (s1b < 64 || s1b >= 192);
    int ra = (s1a < 64) ? s1a : s1a - 128;
    int rb = (s1b < 64) ? s1b : s1b - 128;

    // layer 1 via tables -> hq
#pragma unroll
    for (int oo = 0; oo < 8; oo++){
        int o = ob + oo;
        float2 C  = g_tabC[b*32 + o];
        float2 A0 = g_tabA[s1a*32 + o], B0 = g_tabB[m2a*32 + o];
        float2 A1 = g_tabA[s1b*32 + o], B1 = g_tabB[m2b*32 + o];
        hq[o*128 + 2*pr]     = make_float2(gelu1(A0.x+B0.x+C.x), gelu1(A0.y+B0.y+C.y));
        hq[o*128 + 2*pr + 1] = make_float2(gelu1(A1.x+B1.x+C.x), gelu1(A1.y+B1.y+C.y));
    }
    __syncthreads();

    const ulonglong2* w2u = (const ulonglong2*)sw2t;
    const ulonglong2* w0u = (const ulonglong2*)sw0;

    // layer 2: 32->32
    ull a1[2][8], a2[2][8];
#pragma unroll
    for (int oo = 0; oo < 8; oo++){
        ull bb = pk(b2r[ob+oo], b2i[ob+oo]);
        a1[0][oo] = bb; a1[1][oo] = bb;
        a2[0][oo] = 0ull; a2[1][oo] = 0ull;
    }
#pragma unroll 4
    for (int i = 0; i < 32; i++){
        ulonglong2 uu = *(const ulonglong2*)(hq + i*128 + 2*pr);
        float r0,i0,r1,i1;
        upk(uu.x, r0, i0); upk(uu.y, r1, i1);
        ull ur0 = pk(r0,r0), ui0 = pk(i0,i0), ur1 = pk(r1,r1), ui1 = pk(i1,i1);
#pragma unroll
        for (int j = 0; j < 4; j++){
            ulonglong2 w = w2u[(i*32 + ob)/2 + j];
            ffma2(a1[0][2*j],   ur0, w.x); ffma2(a2[0][2*j],   ui0, w.x);
            ffma2(a1[0][2*j+1], ur0, w.y); ffma2(a2[0][2*j+1], ui0, w.y);
            ffma2(a1[1][2*j],   ur1, w.x); ffma2(a2[1][2*j],   ui1, w.x);
            ffma2(a1[1][2*j+1], ur1, w.y); ffma2(a2[1][2*j+1], ui1, w.y);
        }
    }

    // re_feature -> x*rf -> mask -> +1  (both pixels)
    float qr[2][8], qi[2][8];
    const float2* xr2 = (const float2*)xr;
    const float2* xi2 = (const float2*)xi;
#pragma unroll
    for (int oo = 0; oo < 8; oo++){
        int o = ob + oo;
        float2 vr = xr2[(xoff + o*PLANE) >> 1];
        float2 vi = xi2[(xoff + o*PLANE) >> 1];
        float p1,q1,r1,s1;
        upk(a1[0][oo], p1, q1); upk(a2[0][oo], r1, s1);
        {
            float ar = p1 - s1, ai = q1 + r1;
            float zr = vr.x*ar - vi.x*ai;
            float zi = vr.x*ai + vi.x*ar;
            bool keep = (zr*zr + zi*zi) > 0.0025f;
            qr[0][oo] = (keep ? zr : 0.0f) + 1.0f;
            qi[0][oo] =  keep ? zi : 0.0f;
        }
        upk(a1[1][oo], p1, q1); upk(a2[1][oo], r1, s1);
        {
            float ar = p1 - s1, ai = q1 + r1;
            float zr = vr.y*ar - vi.y*ai;
            float zi = vr.y*ai + vi.y*ar;
            bool keep = (zr*zr + zi*zi) > 0.0025f;
            qr[1][oo] = (keep ? zr : 0.0f) + 1.0f;
            qi[1][oo] =  keep ? zi : 0.0f;
        }
    }
    __syncthreads();
#pragma unroll
    for (int oo = 0; oo < 8; oo++){
        int o = ob + oo;
        hq[o*128 + 2*pr]     = make_float2(qr[0][oo], qi[0][oo]);
        hq[o*128 + 2*pr + 1] = make_float2(qr[1][oo], qi[1][oo]);
    }
    __syncthreads();

    // layer 3: W0 ('io')
#pragma unroll
    for (int oo = 0; oo < 8; oo++){
        a1[0][oo] = 0ull; a1[1][oo] = 0ull;
        a2[0][oo] = 0ull; a2[1][oo] = 0ull;
    }
#pragma unroll 4
    for (int i = 0; i < 32; i++){
        ulonglong2 uu = *(const ulonglong2*)(hq + i*128 + 2*pr);
        float r0,i0,r1,i1;
        upk(uu.x, r0, i0); upk(uu.y, r1, i1);
        ull ur0 = pk(r0,r0), ui0 = pk(i0,i0), ur1 = pk(r1,r1), ui1 = pk(i1,i1);
#pragma unroll
        for (int j = 0; j < 4; j++){
            ulonglong2 w = w0u[(i*32 + ob)/2 + j];
            ffma2(a1[0][2*j],   ur0, w.x); ffma2(a2[0][2*j],   ui0, w.x);
            ffma2(a1[0][2*j+1], ur0, w.y); ffma2(a2[0][2*j+1], ui0, w.y);
            ffma2(a1[1][2*j],   ur1, w.x); ffma2(a2[1][2*j],   ui1, w.x);
            ffma2(a1[1][2*j+1], ur1, w.y); ffma2(a2[1][2*j+1], ui1, w.y);
        }
    }
#pragma unroll
    for (int oo = 0; oo < 8; oo++){
        float p1,q1,r1,s1;
        int o   = ob + oo;
        int idx = xoff + o*PLANE;                // even
        upk(a1[0][oo], p1, q1); upk(a2[0][oo], r1, s1);
        float gr0 = gelu1(p1 - s1), gi0 = gelu1(q1 + r1);
        upk(a1[1][oo], p1, q1); upk(a2[1][oo], r1, s1);
        float gr1 = gelu1(p1 - s1), gi1 = gelu1(q1 + r1);
        // real parts -> out (xs0 region + skip0 region)
        ((float2*)out)[idx >> 1] = make_float2(gr0, gr1);
        ((float2*)out)[(OFF_SKIP0 + idx) >> 1] = make_float2(gr0, gr1);
        // complex -> compact corner buffer only (down1's sole input)
        if (ca) g_c0[((b*32 + o) << 13) + (ra << 6) + m2a] = make_float2(gr0, gi0);
        if (cb) g_c0[((b*32 + o) << 13) + (rb << 6) + m2b] = make_float2(gr1, gi1);
    }
}

// ---------------- K2: down1 (32->64), 64 px/block, 2 px/thread ----------------
__global__ void __launch_bounds__(256, 3)
k_down1(const float* __restrict__ wr_g, const float* __restrict__ wi_g,
        float* __restrict__ out)
{
    __shared__ __align__(16) float2 sw[2048];     // wd1 [i*64+o]  16KB
    __shared__ __align__(16) float2 in_s[2048];   // [i][px]       16KB
    for (int t = threadIdx.x; t < 2048; t += 256) sw[t] = make_float2(wr_g[t], wi_g[t]);

    int p0 = blockIdx.x * 64;                     // 1024 blocks; one (b,r) row each
    for (int k = threadIdx.x; k < 2048; k += 256){
        int px = k & 63, i = k >> 6;
        int p = p0 + px;
        int b = p >> 13, r = (p & 8191) >> 6, c = p & 63;
        in_s[i*64 + px] = g_c0[((b*32 + i) << 13) + (r << 6) + c];   // coalesced
    }
    __syncthreads();

    const ulonglong2* wu = (const ulonglong2*)sw;
    int pr = threadIdx.x & 31, ob = (threadIdx.x >> 5) * 8;
    int p = p0 + 2*pr;
    int b = p >> 13, r = (p & 8191) >> 6, c = p & 63;
    int dst = b * 64 * 8192 + r * 64 + c;         // even

    ull a1[2][8], a2[2][8];
#pragma unroll
    for (int oo = 0; oo < 8; oo++){
        a1[0][oo]=0ull; a1[1][oo]=0ull; a2[0][oo]=0ull; a2[1][oo]=0ull;
    }
#pragma unroll 4
    for (int i = 0; i < 32; i++){
        ulonglong2 uu = *(const ulonglong2*)(in_s + i*64 + 2*pr);
        float r0,i0,r1,i1;
        upk(uu.x, r0, i0); upk(uu.y, r1, i1);
        ull ur0 = pk(r0,r0), ui0 = pk(i0,i0), ur1 = pk(r1,r1), ui1 = pk(i1,i1);
#pragma unroll
        for (int j = 0; j < 4; j++){
            ulonglong2 w = wu[(i*64 + ob)/2 + j];
            ffma2(a1[0][2*j],   ur0, w.x); ffma2(a2[0][2*j],   ui0, w.x);
            ffma2(a1[0][2*j+1], ur0, w.y); ffma2(a2[0][2*j+1], ui0, w.y);
            ffma2(a1[1][2*j],   ur1, w.x); ffma2(a2[1][2*j],   ui1, w.x);
            ffma2(a1[1][2*j+1], ur1, w.y); ffma2(a2[1][2*j+1], ui1, w.y);
        }
    }
#pragma unroll
    for (int oo = 0; oo < 8; oo++){
        int o = ob + oo;
        float p1,q1,r1,s1;
        upk(a1[0][oo], p1, q1); upk(a2[0][oo], r1, s1);
        float gr0 = gelu1(p1 - s1) + 1.0f, gi0 = gelu1(q1 + r1);
        upk(a1[1][oo], p1, q1); upk(a2[1][oo], r1, s1);
        float gr1 = gelu1(p1 - s1) + 1.0f, gi1 = gelu1(q1 + r1);
        ulonglong2 st; st.x = pk(gr0, gi0); st.y = pk(gr1, gi1);
        *(ulonglong2*)(g_x1_1 + dst + o*8192) = st;
        ((float2*)out)[(OFF_SKIP1 + dst + o*8192) >> 1] = make_float2(gr0, gr1);
    }
}

// ---------------- K3: fused down2+up2 (256 thr, 2 px x 4 outs) ----------------
__global__ void __launch_bounds__(256, 4)
k_mid(const float* __restrict__ wdr, const float* __restrict__ wdi,
      const float* __restrict__ wur, const float* __restrict__ wui,
      float* __restrict__ out)
{
    __shared__ __align__(16) float2 sw[4096];     // wd2 then wu2, [i*64+o]  32KB
    __shared__ __align__(16) float2 in_s[2048];   // x1_1 corners, then sk2  16KB
    for (int t = threadIdx.x; t < 4096; t += 256) sw[t] = make_float2(wdr[t], wdi[t]);

    int p0 = blockIdx.x * 32;                     // 512 blocks
    for (int k = threadIdx.x; k < 2048; k += 256){
        int px = k & 31, i = k >> 5;
        int p = p0 + px;
        int b = p >> 11, r = (p & 2047) >> 5, c = p & 31;
        int srow = (r < 32) ? r : r + 64;
        in_s[i*32 + px] = g_x1_1[b*64*8192 + srow*64 + c + i*8192];
    }
    __syncthreads();

    const ulonglong2* wu = (const ulonglong2*)sw;
    int pr = threadIdx.x & 15, ob = (threadIdx.x >> 4) * 4;   // 4 outputs/thread
    int p = p0 + 2*pr;
    int b = p >> 11, r = (p & 2047) >> 5, c = p & 31;
    int dst2 = b * 64 * 2048 + r * 32 + c;        // skip2 index (even)
    int srow = (r < 32) ? r : r + 64;
    int dst1 = b * 64 * 8192 + srow * 64 + c;     // x1_1 corner index (even)

    // ---- phase 1: sk2 = cgelu(x2 @ Wd2) + 1 ----
    ull a1[2][4], a2[2][4];
#pragma unroll
    for (int k = 0; k < 4; k++){
        a1[0][k]=0ull; a1[1][k]=0ull; a2[0][k]=0ull; a2[1][k]=0ull;
    }
#pragma unroll 4
    for (int i = 0; i < 64; i++){
        ulonglong2 uu = *(const ulonglong2*)(in_s + i*32 + 2*pr);
        float r0,i0,r1,i1;
        upk(uu.x, r0, i0); upk(uu.y, r1, i1);
        ull ur0 = pk(r0,r0), ui0 = pk(i0,i0), ur1 = pk(r1,r1), ui1 = pk(i1,i1);
#pragma unroll
        for (int j = 0; j < 2; j++){
            ulonglong2 w = wu[(i*64 + ob)/2 + j];
            ffma2(a1[0][2*j],   ur0, w.x); ffma2(a2[0][2*j],   ui0, w.x);
            ffma2(a1[0][2*j+1], ur0, w.y); ffma2(a2[0][2*j+1], ui0, w.y);
            ffma2(a1[1][2*j],   ur1, w.x); ffma2(a2[1][2*j],   ui1, w.x);
            ffma2(a1[1][2*j+1], ur1, w.y); ffma2(a2[1][2*j+1], ui1, w.y);
        }
    }
    float skr[2][4], ski[2][4];
#pragma unroll
    for (int k = 0; k < 4; k++){
        int o = ob + k;
        float p1,q1,r1,s1;
        upk(a1[0][k], p1, q1); upk(a2[0][k], r1, s1);
        skr[0][k] = gelu1(p1 - s1) + 1.0f; ski[0][k] = gelu1(q1 + r1);
        upk(a1[1][k], p1, q1); upk(a2[1][k], r1, s1);
        skr[1][k] = gelu1(p1 - s1) + 1.0f; ski[1][k] = gelu1(q1 + r1);
        ((float2*)out)[(OFF_SKIP2 + dst2 + o*2048) >> 1] = make_float2(skr[0][k], skr[1][k]);
    }

    // ---- exchange sk2 through smem; swap weights to Wu2 ----
    __syncthreads();
#pragma unroll
    for (int k = 0; k < 4; k++){
        int o = ob + k;
        in_s[o*32 + 2*pr]     = make_float2(skr[0][k], ski[0][k]);
        in_s[o*32 + 2*pr + 1] = make_float2(skr[1][k], ski[1][k]);
    }
    for (int t = threadIdx.x; t < 4096; t += 256) sw[t] = make_float2(wur[t], wui[t]);
    __syncthreads();

    // ---- phase 2: u = cgelu(sk2 @ Wu2); x1_1 += u; out skip1 = x1_1.re ----
#pragma unroll
    for (int k = 0; k < 4; k++){
        a1[0][k]=0ull; a1[1][k]=0ull; a2[0][k]=0ull; a2[1][k]=0ull;
    }
#pragma unroll 4
    for (int i = 0; i < 64; i++){
        ulonglong2 uu = *(const ulonglong2*)(in_s + i*32 + 2*pr);
        float r0,i0,r1,i1;
        upk(uu.x, r0, i0); upk(uu.y, r1, i1);
        ull ur0 = pk(r0,r0), ui0 = pk(i0,i0), ur1 = pk(r1,r1), ui1 = pk(i1,i1);
#pragma unroll
        for (int j = 0; j < 2; j++){
            ulonglong2 w = wu[(i*64 + ob)/2 + j];
            ffma2(a1[0][2*j],   ur0, w.x); ffma2(a2[0][2*j],   ui0, w.x);
            ffma2(a1[0][2*j+1], ur0, w.y); ffma2(a2[0][2*j+1], ui0, w.y);
            ffma2(a1[1][2*j],   ur1, w.x); ffma2(a2[1][2*j],   ui1, w.x);
            ffma2(a1[1][2*j+1], ur1, w.y); ffma2(a2[1][2*j+1], ui1, w.y);
        }
    }
#pragma unroll
    for (int k = 0; k < 4; k++){
        int o = ob + k;
        float p1,q1,r1,s1;
        upk(a1[0][k], p1, q1); upk(a2[0][k], r1, s1);
        float u0r = gelu1(p1 - s1), u0i = gelu1(q1 + r1);
        upk(a1[1][k], p1, q1); upk(a2[1][k], r1, s1);
        float u1r = gelu1(p1 - s1), u1i = gelu1(q1 + r1);
        ulonglong2 old = *(const ulonglong2*)(g_x1_1 + dst1 + o*8192);
        float o0r,o0i,o1r,o1i;
        upk(old.x, o0r, o0i); upk(old.y, o1r, o1i);
        float n0r = o0r + u0r, n0i = o0i + u0i;
        float n1r = o1r + u1r, n1i = o1i + u1i;
        ulonglong2 st; st.x = pk(n0r, n0i); st.y = pk(n1r, n1i);
        *(ulonglong2*)(g_x1_1 + dst1 + o*8192) = st;
        ((float2*)out)[(OFF_SKIP1 + dst1 + o*8192) >> 1] = make_float2(n0r, n1r);
    }
}

// ---------------- K4: up1 (64->32, real-only, 2 px + output-pair packing) ----------------
__global__ void __launch_bounds__(256, 3)
k_up1(const float* __restrict__ wr_g, const float* __restrict__ wi_g,
      float* __restrict__ out)
{
    __shared__ __align__(16) ulonglong2 sw4[1024];   // [i*16+op] 16KB
    __shared__ __align__(16) float2 in_s[4096];      // [i][px] 64ch x 64px = 32KB
    for (int t = threadIdx.x; t < 1024; t += 256){
        int i = t >> 4, op = t & 15;
        ulonglong2 v;
        v.x = pk(wr_g[i*32 + 2*op], wr_g[i*32 + 2*op + 1]);
        v.y = pk(wi_g[i*32 + 2*op], wi_g[i*32 + 2*op + 1]);
        sw4[t] = v;
    }

    int p0 = blockIdx.x * 64;                        // 1024 blocks
    for (int k = threadIdx.x; k < 4096; k += 256){
        int px = k & 63, i = k >> 6;
        int p = p0 + px;
        int b = p >> 13, r = (p & 8191) >> 6, c = p & 63;
        in_s[i*64 + px] = g_x1_1[b*64*8192 + r*64 + c + i*8192];   // final skip1
    }
    __syncthreads();

    int pr = threadIdx.x & 31, og = threadIdx.x >> 5;  // og: 2 output-pairs (4 outputs)
    int p = p0 + 2*pr;
    int b = p >> 13, r = (p & 8191) >> 6, c = p & 63;
    int drow = (r < 64) ? r : r + 128;
    int dst = b * 32 * PLANE + drow * M2C + c;

    ull a1[2][2] = {{0ull,0ull},{0ull,0ull}};
    ull a2[2][2] = {{0ull,0ull},{0ull,0ull}};
#pragma unroll 4
    for (int i = 0; i < 64; i++){
        ulonglong2 uu = *(const ulonglong2*)(in_s + i*64 + 2*pr);
        float r0,i0,r1,i1;
        upk(uu.x, r0, i0); upk(uu.y, r1, i1);
        ull ur0 = pk(r0,r0), ui0 = pk(i0,i0), ur1 = pk(r1,r1), ui1 = pk(i1,i1);
#pragma unroll
        for (int j = 0; j < 2; j++){
            ulonglong2 w = sw4[i*16 + og*2 + j];
            ffma2(a1[0][j], ur0, w.x); ffma2(a2[0][j], ui0, w.y);
            ffma2(a1[1][j], ur1, w.x); ffma2(a2[1][j], ui1, w.y);
        }
    }
#pragma unroll
    for (int j = 0; j < 2; j++){
        int o = og*4 + 2*j;
        float x0,x1,y0,y1;
        upk(a1[0][j], x0, x1); upk(a2[0][j], y0, y1);
        {
            int idx = dst + o*PLANE;
            float v = out[idx] + gelu1(x0 - y0);
            out[idx] = v; out[OFF_SKIP0 + idx] = v;
            idx = dst + (o+1)*PLANE;
            v = out[idx] + gelu1(x1 - y1);
            out[idx] = v; out[OFF_SKIP0 + idx] = v;
        }
        upk(a1[1][j], x0, x1); upk(a2[1][j], y0, y1);
        {
            int idx = dst + 1 + o*PLANE;
            float v = out[idx] + gelu1(x0 - y0);
            out[idx] = v; out[OFF_SKIP0 + idx] = v;
            idx = dst + 1 + (o+1)*PLANE;
            v = out[idx] + gelu1(x1 - y1);
            out[idx] = v; out[OFF_SKIP0 + idx] = v;
        }
    }
}

// ---------------- launch ----------------
extern "C" void kernel_launch(void* const* d_in, const int* in_sizes, int n_in,
                              void* d_out, int out_size)
{
    const float* xr   = (const float*)d_in[0];
    const float* xi   = (const float*)d_in[1];
    const float* Re   = (const float*)d_in[2];
    const float* w1r  = (const float*)d_in[3];
    const float* w1i  = (const float*)d_in[4];
    const float* b1r  = (const float*)d_in[5];
    const float* b1i  = (const float*)d_in[6];
    const float* w2r  = (const float*)d_in[7];
    const float* w2i  = (const float*)d_in[8];
    const float* b2r  = (const float*)d_in[9];
    const float* b2i  = (const float*)d_in[10];
    const float* w0r  = (const float*)d_in[11];
    const float* w0i  = (const float*)d_in[12];
    const float* wd1r = (const float*)d_in[13];
    const float* wd1i = (const float*)d_in[14];
    const float* wu1r = (const float*)d_in[15];
    const float* wu1i = (const float*)d_in[16];
    const float* wd2r = (const float*)d_in[17];
    const float* wd2i = (const float*)d_in[18];
    const float* wu2r = (const float*)d_in[19];
    const float* wu2i = (const float*)d_in[20];

    float* out = (float*)d_out;

    k_prep  <<<51, 256>>>(Re, w1r, w1i, b1r, b1i);
    k_level0<<<2064, 256>>>(xr, xi, w2r, w2i, b2r, b2i, w0r, w0i, out);
    k_down1 <<<1024, 256>>>(wd1r, wd1i, out);
    k_mid   <<<512,  256>>>(wd2r, wd2i, wu2r, wu2i, out);
    k_up1   <<<1024, 256>>>(wu1r, wu1i, out);
}

// round 16
// speedup vs baseline: 1.0352x; 1.0352x over previous
#include <cuda_runtime.h>

typedef unsigned long long ull;

// ---------------- problem constants ----------------
#define BB 8
#define S1C 256
#define M2C 129
#define PLANE (S1C*M2C)            // 33024
#define N0 (BB*32*PLANE)           // 8454144
#define N1 (BB*64*128*64)          // 4194304
#define N2 (BB*64*64*32)           // 1048576
#define OFF_SKIP0 (N0)
#define OFF_SKIP1 (2*N0)
#define OFF_SKIP2 (2*N0+N1)

// complex scratch (16B-aligned for vector access)
__device__ __align__(16) float2 g_c0[BB*32*128*64];  // x1_0 CORNERS ONLY, [b][ch][r][c] (16.8MB)
__device__ __align__(16) float2 g_x1_1[N1];
// level-0 layer-1 separable tables: pre-act = A(s1) + B(m2) + C(b)
__device__ float2 g_tabA[256*32];
__device__ float2 g_tabB[129*32];
__device__ float2 g_tabC[8*32];

// ---------------- packed f32x2 helpers ----------------
__device__ __forceinline__ ull pk(float x, float y){
    ull r; asm("mov.b64 %0, {%1,%2};" : "=l"(r) : "f"(x), "f"(y)); return r;
}
__device__ __forceinline__ void upk(ull v, float& x, float& y){
    asm("mov.b64 {%0,%1}, %2;" : "=f"(x), "=f"(y) : "l"(v));
}
__device__ __forceinline__ void ffma2(ull& d, ull a, ull b){
    asm("fma.rn.f32x2 %0, %1, %2, %0;" : "+l"(d) : "l"(a), "l"(b));
}

__device__ __forceinline__ float gelu1(float v){
    float u = 0.7978845608028654f * v * fmaf(0.044715f * v, v, 1.0f);
    float t;
    asm("tanh.approx.f32 %0, %1;" : "=f"(t) : "f"(u));
    return 0.5f * v * (1.0f + t);
}

__device__ __forceinline__ void kpow3(float kv, float* r0, float* i0,
                                      float* r1, float* i1, float* r2, float* i2){
    float a  = fabsf(kv);
    float c1 = cbrtf(a);
    float c2 = c1 * c1;
    if (kv >= 0.0f){
        *r0 = c1;        *i0 = 0.0f;
        *r1 = c2;        *i1 = 0.0f;
        *r2 = a;         *i2 = 0.0f;
    } else {
        *r0 =  0.5f*c1;  *i0 = 0.86602540f*c1;
        *r1 = -0.5f*c2;  *i1 = 0.86602540f*c2;
        *r2 = -a;        *i2 = 0.0f;
    }
}

// ---------------- K0: prep separable layer-1 tables ----------------
__global__ void k_prep(const float* __restrict__ Re,
                       const float* __restrict__ w1r, const float* __restrict__ w1i,
                       const float* __restrict__ b1r, const float* __restrict__ b1i)
{
    int idx = blockIdx.x * 256 + threadIdx.x;
    if (idx < 8192){                                    // A[s1][o]
        int s1 = idx >> 5, o = idx & 31;
        float kv = (s1 < 128) ? (float)s1 : (float)(s1 - 256);
        float f0r,f0i,f1r,f1i,f2r,f2i;
        kpow3(kv, &f0r,&f0i, &f1r,&f1i, &f2r,&f2i);
        float2 a = make_float2(0,0);
        float2 w;
        w = make_float2(w1r[o*9+0], w1i[o*9+0]); a.x += w.x*f0r - w.y*f0i; a.y += w.x*f0i + w.y*f0r;
        w = make_float2(w1r[o*9+2], w1i[o*9+2]); a.x += w.x*f1r - w.y*f1i; a.y += w.x*f1i + w.y*f1r;
        w = make_float2(w1r[o*9+4], w1i[o*9+4]); a.x += w.x*f2r - w.y*f2i; a.y += w.x*f2i + w.y*f2r;
        g_tabA[idx] = a;
    } else if (idx < 8192 + 4128){                      // B[m2][o]
        int j = idx - 8192;
        int m2 = j / 32, o = j % 32;
        float kv = (m2 < 128) ? (float)m2 : -128.0f;
        float f0r,f0i,f1r,f1i,f2r,f2i;
        kpow3(kv, &f0r,&f0i, &f1r,&f1i, &f2r,&f2i);
        float2 a = make_float2(0,0);
        float2 w;
        w = make_float2(w1r[o*9+1], w1i[o*9+1]); a.x += w.x*f0r - w.y*f0i; a.y += w.x*f0i + w.y*f0r;
        w = make_float2(w1r[o*9+3], w1i[o*9+3]); a.x += w.x*f1r - w.y*f1i; a.y += w.x*f1i + w.y*f1r;
        w = make_float2(w1r[o*9+5], w1i[o*9+5]); a.x += w.x*f2r - w.y*f2i; a.y += w.x*f2i + w.y*f2r;
        g_tabB[j] = a;
    } else if (idx < 8192 + 4128 + 256){                // C[b][o]
        int j = idx - 8192 - 4128;
        int b = j >> 5, o = j & 31;
        float r = Re[b];
        float c1 = cbrtf(r), c2 = c1*c1;
        float2 a = make_float2(b1r[o], b1i[o]);
        a.x += w1r[o*9+6]*c1; a.y += w1i[o*9+6]*c1;
        a.x += w1r[o*9+7]*c2; a.y += w1i[o*9+7]*c2;
        a.x += w1r[o*9+8]*r;  a.y += w1i[o*9+8]*r;
        g_tabC[j] = a;
    }
}

// ---------------- K1: fused level-0 (128 px/block, 2 px/thread, 8 outs) ----------------
__global__ void __launch_bounds__(256)
k_level0(const float* __restrict__ xr, const float* __restrict__ xi,
         const float* __restrict__ w2r, const float* __restrict__ w2i,
         const float* __restrict__ b2r, const float* __restrict__ b2i,
         const float* __restrict__ w0r, const float* __restrict__ w0i,
         float* __restrict__ out)
{
    __shared__ __align__(16) float2 sw2t[1024];   // w2 transposed to [i*32+o]  8KB
    __shared__ __align__(16) float2 sw0[1024];    // w0 already [i*32+o]        8KB
    __shared__ __align__(16) float2 hq[32*128];   // [ch][px] exchange          32KB

    for (int t = threadIdx.x; t < 1024; t += 256){
        int o = t >> 5, i = t & 31;
        sw2t[i*32 + o] = make_float2(w2r[t], w2i[t]);
        sw0[t]         = make_float2(w0r[t], w0i[t]);
    }

    int tid = threadIdx.x;
    int pr  = tid & 63;               // pixel-pair id
    int ob  = (tid >> 6) * 8;         // 0,8,16,24
    int p0  = blockIdx.x * 128 + 2*pr;
    int b   = p0 / PLANE;
    int sp0 = p0 - b * PLANE;
    int s1a = sp0 / M2C;
    int m2a = sp0 - s1a * M2C;
    int s1b = s1a, m2b = m2a + 1;
    if (m2b == M2C){ m2b = 0; s1b = s1a + 1; }
    int xoff = b * 32 * PLANE + sp0;  // even

    // corner membership (for compact complex store)
    bool ca = (m2a < 64) && (s1a < 64 || s1a >= 192);
    bool cb = (m2b < 64) && (s1b < 64 || s1b >= 192);
    int ra = (s1a < 64) ? s1a : s1a - 128;
    int rb = (s1b < 64) ? s1b : s1b - 128;

    // layer 1 via tables -> hq
#pragma unroll
    for (int oo = 0; oo < 8; oo++){
        int o = ob + oo;
        float2 C  = g_tabC[b*32 + o];
        float2 A0 = g_tabA[s1a*32 + o], B0 = g_tabB[m2a*32 + o];
        float2 A1 = g_tabA[s1b*32 + o], B1 = g_tabB[m2b*32 + o];
        hq[o*128 + 2*pr]     = make_float2(gelu1(A0.x+B0.x+C.x), gelu1(A0.y+B0.y+C.y));
        hq[o*128 + 2*pr + 1] = make_float2(gelu1(A1.x+B1.x+C.x), gelu1(A1.y+B1.y+C.y));
    }
    __syncthreads();

    const ulonglong2* w2u = (const ulonglong2*)sw2t;
    const ulonglong2* w0u = (const ulonglong2*)sw0;

    // layer 2: 32->32
    ull a1[2][8], a2[2][8];
#pragma unroll
    for (int oo = 0; oo < 8; oo++){
        ull bb = pk(b2r[ob+oo], b2i[ob+oo]);
        a1[0][oo] = bb; a1[1][oo] = bb;
        a2[0][oo] = 0ull; a2[1][oo] = 0ull;
    }
#pragma unroll 4
    for (int i = 0; i < 32; i++){
        ulonglong2 uu = *(const ulonglong2*)(hq + i*128 + 2*pr);
        float r0,i0,r1,i1;
        upk(uu.x, r0, i0); upk(uu.y, r1, i1);
        ull ur0 = pk(r0,r0), ui0 = pk(i0,i0), ur1 = pk(r1,r1), ui1 = pk(i1,i1);
#pragma unroll
        for (int j = 0; j < 4; j++){
            ulonglong2 w = w2u[(i*32 + ob)/2 + j];
            ffma2(a1[0][2*j],   ur0, w.x); ffma2(a2[0][2*j],   ui0, w.x);
            ffma2(a1[0][2*j+1], ur0, w.y); ffma2(a2[0][2*j+1], ui0, w.y);
            ffma2(a1[1][2*j],   ur1, w.x); ffma2(a2[1][2*j],   ui1, w.x);
            ffma2(a1[1][2*j+1], ur1, w.y); ffma2(a2[1][2*j+1], ui1, w.y);
        }
    }

    // re_feature -> x*rf -> mask -> +1  (both pixels)
    float qr[2][8], qi[2][8];
    const float2* xr2 = (const float2*)xr;
    const float2* xi2 = (const float2*)xi;
#pragma unroll
    for (int oo = 0; oo < 8; oo++){
        int o = ob + oo;
        float2 vr = xr2[(xoff + o*PLANE) >> 1];
        float2 vi = xi2[(xoff + o*PLANE) >> 1];
        float p1,q1,r1,s1;
        upk(a1[0][oo], p1, q1); upk(a2[0][oo], r1, s1);
        {
            float ar = p1 - s1, ai = q1 + r1;
            float zr = vr.x*ar - vi.x*ai;
            float zi = vr.x*ai + vi.x*ar;
            bool keep = (zr*zr + zi*zi) > 0.0025f;
            qr[0][oo] = (keep ? zr : 0.0f) + 1.0f;
            qi[0][oo] =  keep ? zi : 0.0f;
        }
        upk(a1[1][oo], p1, q1); upk(a2[1][oo], r1, s1);
        {
            float ar = p1 - s1, ai = q1 + r1;
            float zr = vr.y*ar - vi.y*ai;
            float zi = vr.y*ai + vi.y*ar;
            bool keep = (zr*zr + zi*zi) > 0.0025f;
            qr[1][oo] = (keep ? zr : 0.0f) + 1.0f;
            qi[1][oo] =  keep ? zi : 0.0f;
        }
    }
    __syncthreads();
#pragma unroll
    for (int oo = 0; oo < 8; oo++){
        int o = ob + oo;
        hq[o*128 + 2*pr]     = make_float2(qr[0][oo], qi[0][oo]);
        hq[o*128 + 2*pr + 1] = make_float2(qr[1][oo], qi[1][oo]);
    }
    __syncthreads();

    // layer 3: W0 ('io')
#pragma unroll
    for (int oo = 0; oo < 8; oo++){
        a1[0][oo] = 0ull; a1[1][oo] = 0ull;
        a2[0][oo] = 0ull; a2[1][oo] = 0ull;
    }
#pragma unroll 4
    for (int i = 0; i < 32; i++){
        ulonglong2 uu = *(const ulonglong2*)(hq + i*128 + 2*pr);
        float r0,i0,r1,i1;
        upk(uu.x, r0, i0); upk(uu.y, r1, i1);
        ull ur0 = pk(r0,r0), ui0 = pk(i0,i0), ur1 = pk(r1,r1), ui1 = pk(i1,i1);
#pragma unroll
        for (int j = 0; j < 4; j++){
            ulonglong2 w = w0u[(i*32 + ob)/2 + j];
            ffma2(a1[0][2*j],   ur0, w.x); ffma2(a2[0][2*j],   ui0, w.x);
            ffma2(a1[0][2*j+1], ur0, w.y); ffma2(a2[0][2*j+1], ui0, w.y);
            ffma2(a1[1][2*j],   ur1, w.x); ffma2(a2[1][2*j],   ui1, w.x);
            ffma2(a1[1][2*j+1], ur1, w.y); ffma2(a2[1][2*j+1], ui1, w.y);
        }
    }
#pragma unroll
    for (int oo = 0; oo < 8; oo++){
        float p1,q1,r1,s1;
        int o   = ob + oo;
        int idx = xoff + o*PLANE;                // even
        upk(a1[0][oo], p1, q1); upk(a2[0][oo], r1, s1);
        float gr0 = gelu1(p1 - s1), gi0 = gelu1(q1 + r1);
        upk(a1[1][oo], p1, q1); upk(a2[1][oo], r1, s1);
        float gr1 = gelu1(p1 - s1), gi1 = gelu1(q1 + r1);
        // real parts -> out (xs0 region + skip0 region)
        ((float2*)out)[idx >> 1] = make_float2(gr0, gr1);
        ((float2*)out)[(OFF_SKIP0 + idx) >> 1] = make_float2(gr0, gr1);
        // complex -> compact corner buffer only (down1's sole input)
        if (ca) g_c0[((b*32 + o) << 13) + (ra << 6) + m2a] = make_float2(gr0, gi0);
        if (cb) g_c0[((b*32 + o) << 13) + (rb << 6) + m2b] = make_float2(gr1, gi1);
    }
}

// ---------------- K2: down1 (32->64), 64 px/block, 2 px/thread ----------------
__global__ void __launch_bounds__(256)
k_down1(const float* __restrict__ wr_g, const float* __restrict__ wi_g,
        float* __restrict__ out)
{
    __shared__ __align__(16) float2 sw[2048];     // wd1 [i*64+o]  16KB
    __shared__ __align__(16) float2 in_s[2048];   // [i][px]       16KB
    for (int t = threadIdx.x; t < 2048; t += 256) sw[t] = make_float2(wr_g[t], wi_g[t]);

    int p0 = blockIdx.x * 64;                     // 1024 blocks; one (b,r) row each
    for (int k = threadIdx.x; k < 2048; k += 256){
        int px = k & 63, i = k >> 6;
        int p = p0 + px;
        int b = p >> 13, r = (p & 8191) >> 6, c = p & 63;
        in_s[i*64 + px] = g_c0[((b*32 + i) << 13) + (r << 6) + c];   // coalesced
    }
    __syncthreads();

    const ulonglong2* wu = (const ulonglong2*)sw;
    int pr = threadIdx.x & 31, ob = (threadIdx.x >> 5) * 8;
    int p = p0 + 2*pr;
    int b = p >> 13, r = (p & 8191) >> 6, c = p & 63;
    int dst = b * 64 * 8192 + r * 64 + c;         // even

    ull a1[2][8], a2[2][8];
#pragma unroll
    for (int oo = 0; oo < 8; oo++){
        a1[0][oo]=0ull; a1[1][oo]=0ull; a2[0][oo]=0ull; a2[1][oo]=0ull;
    }
#pragma unroll 4
    for (int i = 0; i < 32; i++){
        ulonglong2 uu = *(const ulonglong2*)(in_s + i*64 + 2*pr);
        float r0,i0,r1,i1;
        upk(uu.x, r0, i0); upk(uu.y, r1, i1);
        ull ur0 = pk(r0,r0), ui0 = pk(i0,i0), ur1 = pk(r1,r1), ui1 = pk(i1,i1);
#pragma unroll
        for (int j = 0; j < 4; j++){
            ulonglong2 w = wu[(i*64 + ob)/2 + j];
            ffma2(a1[0][2*j],   ur0, w.x); ffma2(a2[0][2*j],   ui0, w.x);
            ffma2(a1[0][2*j+1], ur0, w.y); ffma2(a2[0][2*j+1], ui0, w.y);
            ffma2(a1[1][2*j],   ur1, w.x); ffma2(a2[1][2*j],   ui1, w.x);
            ffma2(a1[1][2*j+1], ur1, w.y); ffma2(a2[1][2*j+1], ui1, w.y);
        }
    }
#pragma unroll
    for (int oo = 0; oo < 8; oo++){
        int o = ob + oo;
        float p1,q1,r1,s1;
        upk(a1[0][oo], p1, q1); upk(a2[0][oo], r1, s1);
        float gr0 = gelu1(p1 - s1) + 1.0f, gi0 = gelu1(q1 + r1);
        upk(a1[1][oo], p1, q1); upk(a2[1][oo], r1, s1);
        float gr1 = gelu1(p1 - s1) + 1.0f, gi1 = gelu1(q1 + r1);
        ulonglong2 st; st.x = pk(gr0, gi0); st.y = pk(gr1, gi1);
        *(ulonglong2*)(g_x1_1 + dst + o*8192) = st;
        ((float2*)out)[(OFF_SKIP1 + dst + o*8192) >> 1] = make_float2(gr0, gr1);
    }
}

// ---------------- K3: fused down2+up2 (128 thr, 16 px/block, 1024 blocks) ----------------
__global__ void __launch_bounds__(128)
k_mid(const float* __restrict__ wdr, const float* __restrict__ wdi,
      const float* __restrict__ wur, const float* __restrict__ wui,
      float* __restrict__ out)
{
    __shared__ __align__(16) float2 sw[4096];     // wd2 then wu2, [i*64+o]  32KB
    __shared__ __align__(16) float2 in_s[1024];   // x1_1 corners, then sk2  8KB
    for (int t = threadIdx.x; t < 4096; t += 128) sw[t] = make_float2(wdr[t], wdi[t]);

    int p0 = blockIdx.x * 16;                     // 1024 blocks
    for (int k = threadIdx.x; k < 1024; k += 128){
        int px = k & 15, i = k >> 4;
        int p = p0 + px;
        int b = p >> 11, r = (p & 2047) >> 5, c = p & 31;
        int srow = (r < 32) ? r : r + 64;
        in_s[i*16 + px] = g_x1_1[b*64*8192 + srow*64 + c + i*8192];
    }
    __syncthreads();

    const ulonglong2* wu = (const ulonglong2*)sw;
    int pr = threadIdx.x & 7, ob = (threadIdx.x >> 3) * 4;    // 8 pairs x 16 groups of 4
    int p = p0 + 2*pr;
    int b = p >> 11, r = (p & 2047) >> 5, c = p & 31;
    int dst2 = b * 64 * 2048 + r * 32 + c;        // skip2 index (even)
    int srow = (r < 32) ? r : r + 64;
    int dst1 = b * 64 * 8192 + srow * 64 + c;     // x1_1 corner index (even)

    // ---- phase 1: sk2 = cgelu(x2 @ Wd2) + 1 ----
    ull a1[2][4], a2[2][4];
#pragma unroll
    for (int k = 0; k < 4; k++){
        a1[0][k]=0ull; a1[1][k]=0ull; a2[0][k]=0ull; a2[1][k]=0ull;
    }
#pragma unroll 4
    for (int i = 0; i < 64; i++){
        ulonglong2 uu = *(const ulonglong2*)(in_s + i*16 + 2*pr);
        float r0,i0,r1,i1;
        upk(uu.x, r0, i0); upk(uu.y, r1, i1);
        ull ur0 = pk(r0,r0), ui0 = pk(i0,i0), ur1 = pk(r1,r1), ui1 = pk(i1,i1);
#pragma unroll
        for (int j = 0; j < 2; j++){
            ulonglong2 w = wu[(i*64 + ob)/2 + j];
            ffma2(a1[0][2*j],   ur0, w.x); ffma2(a2[0][2*j],   ui0, w.x);
            ffma2(a1[0][2*j+1], ur0, w.y); ffma2(a2[0][2*j+1], ui0, w.y);
            ffma2(a1[1][2*j],   ur1, w.x); ffma2(a2[1][2*j],   ui1, w.x);
            ffma2(a1[1][2*j+1], ur1, w.y); ffma2(a2[1][2*j+1], ui1, w.y);
        }
    }
    float skr[2][4], ski[2][4];
#pragma unroll
    for (int k = 0; k < 4; k++){
        int o = ob + k;
        float p1,q1,r1,s1;
        upk(a1[0][k], p1, q1); upk(a2[0][k], r1, s1);
        skr[0][k] = gelu1(p1 - s1) + 1.0f; ski[0][k] = gelu1(q1 + r1);
        upk(a1[1][k], p1, q1); upk(a2[1][k], r1, s1);
        skr[1][k] = gelu1(p1 - s1) + 1.0f; ski[1][k] = gelu1(q1 + r1);
        ((float2*)out)[(OFF_SKIP2 + dst2 + o*2048) >> 1] = make_float2(skr[0][k], skr[1][k]);
    }

    // ---- exchange sk2 through smem; swap weights to Wu2 ----
    __syncthreads();
#pragma unroll
    for (int k = 0; k < 4; k++){
        int o = ob + k;
        in_s[o*16 + 2*pr]     = make_float2(skr[0][k], ski[0][k]);
        in_s[o*16 + 2*pr + 1] = make_float2(skr[1][k], ski[1][k]);
    }
    for (int t = threadIdx.x; t < 4096; t += 128) sw[t] = make_float2(wur[t], wui[t]);
    __syncthreads();

    // ---- phase 2: u = cgelu(sk2 @ Wu2); x1_1 += u; out skip1 = x1_1.re ----
#pragma unroll
    for (int k = 0; k < 4; k++){
        a1[0][k]=0ull; a1[1][k]=0ull; a2[0][k]=0ull; a2[1][k]=0ull;
    }
#pragma unroll 4
    for (int i = 0; i < 64; i++){
        ulonglong2 uu = *(const ulonglong2*)(in_s + i*16 + 2*pr);
        float r0,i0,r1,i1;
        upk(uu.x, r0, i0); upk(uu.y, r1, i1);
        ull ur0 = pk(r0,r0), ui0 = pk(i0,i0), ur1 = pk(r1,r1), ui1 = pk(i1,i1);
#pragma unroll
        for (int j = 0; j < 2; j++){
            ulonglong2 w = wu[(i*64 + ob)/2 + j];
            ffma2(a1[0][2*j],   ur0, w.x); ffma2(a2[0][2*j],   ui0, w.x);
            ffma2(a1[0][2*j+1], ur0, w.y); ffma2(a2[0][2*j+1], ui0, w.y);
            ffma2(a1[1][2*j],   ur1, w.x); ffma2(a2[1][2*j],   ui1, w.x);
            ffma2(a1[1][2*j+1], ur1, w.y); ffma2(a2[1][2*j+1], ui1, w.y);
        }
    }
#pragma unroll
    for (int k = 0; k < 4; k++){
        int o = ob + k;
        float p1,q1,r1,s1;
        upk(a1[0][k], p1, q1); upk(a2[0][k], r1, s1);
        float u0r = gelu1(p1 - s1), u0i = gelu1(q1 + r1);
        upk(a1[1][k], p1, q1); upk(a2[1][k], r1, s1);
        float u1r = gelu1(p1 - s1), u1i = gelu1(q1 + r1);
        ulonglong2 old = *(const ulonglong2*)(g_x1_1 + dst1 + o*8192);
        float o0r,o0i,o1r,o1i;
        upk(old.x, o0r, o0i); upk(old.y, o1r, o1i);
        float n0r = o0r + u0r, n0i = o0i + u0i;
        float n1r = o1r + u1r, n1i = o1i + u1i;
        ulonglong2 st; st.x = pk(n0r, n0i); st.y = pk(n1r, n1i);
        *(ulonglong2*)(g_x1_1 + dst1 + o*8192) = st;
        ((float2*)out)[(OFF_SKIP1 + dst1 + o*8192) >> 1] = make_float2(n0r, n1r);
    }
}

// ---------------- K4: up1 (64->32, real-only, 2 px + output-pair packing) ----------------
__global__ void __launch_bounds__(256)
k_up1(const float* __restrict__ wr_g, const float* __restrict__ wi_g,
      float* __restrict__ out)
{
    __shared__ __align__(16) ulonglong2 sw4[1024];   // [i*16+op] 16KB
    __shared__ __align__(16) float2 in_s[4096];      // [i][px] 64ch x 64px = 32KB
    for (int t = threadIdx.x; t < 1024; t += 256){
        int i = t >> 4, op = t & 15;
        ulonglong2 v;
        v.x = pk(wr_g[i*32 + 2*op], wr_g[i*32 + 2*op + 1]);
        v.y = pk(wi_g[i*32 + 2*op], wi_g[i*32 + 2*op + 1]);
        sw4[t] = v;
    }

    int p0 = blockIdx.x * 64;                        // 1024 blocks
    for (int k = threadIdx.x; k < 4096; k += 256){
        int px = k & 63, i = k >> 6;
        int p = p0 + px;
        int b = p >> 13, r = (p & 8191) >> 6, c = p & 63;
        in_s[i*64 + px] = g_x1_1[b*64*8192 + r*64 + c + i*8192];   // final skip1
    }
    __syncthreads();

    int pr = threadIdx.x & 31, og = threadIdx.x >> 5;  // og: 2 output-pairs (4 outputs)
    int p = p0 + 2*pr;
    int b = p >> 13, r = (p & 8191) >> 6, c = p & 63;
    int drow = (r < 64) ? r : r + 128;
    int dst = b * 32 * PLANE + drow * M2C + c;

    ull a1[2][2] = {{0ull,0ull},{0ull,0ull}};
    ull a2[2][2] = {{0ull,0ull},{0ull,0ull}};
#pragma unroll 4
    for (int i = 0; i < 64; i++){
        ulonglong2 uu = *(const ulonglong2*)(in_s + i*64 + 2*pr);
        float r0,i0,r1,i1;
        upk(uu.x, r0, i0); upk(uu.y, r1, i1);
        ull ur0 = pk(r0,r0), ui0 = pk(i0,i0), ur1 = pk(r1,r1), ui1 = pk(i1,i1);
#pragma unroll
        for (int j = 0; j < 2; j++){
            ulonglong2 w = sw4[i*16 + og*2 + j];
            ffma2(a1[0][j], ur0, w.x); ffma2(a2[0][j], ui0, w.y);
            ffma2(a1[1][j], ur1, w.x); ffma2(a2[1][j], ui1, w.y);
        }
    }
#pragma unroll
    for (int j = 0; j < 2; j++){
        int o = og*4 + 2*j;
        float x0,x1,y0,y1;
        upk(a1[0][j], x0, x1); upk(a2[0][j], y0, y1);
        {
            int idx = dst + o*PLANE;
            float v = out[idx] + gelu1(x0 - y0);
            out[idx] = v; out[OFF_SKIP0 + idx] = v;
            idx = dst + (o+1)*PLANE;
            v = out[idx] + gelu1(x1 - y1);
            out[idx] = v; out[OFF_SKIP0 + idx] = v;
        }
        upk(a1[1][j], x0, x1); upk(a2[1][j], y0, y1);
        {
            int idx = dst + 1 + o*PLANE;
            float v = out[idx] + gelu1(x0 - y0);
            out[idx] = v; out[OFF_SKIP0 + idx] = v;
            idx = dst + 1 + (o+1)*PLANE;
            v = out[idx] + gelu1(x1 - y1);
            out[idx] = v; out[OFF_SKIP0 + idx] = v;
        }
    }
}

// ---------------- launch ----------------
extern "C" void kernel_launch(void* const* d_in, const int* in_sizes, int n_in,
                              void* d_out, int out_size)
{
    const float* xr   = (const float*)d_in[0];
    const float* xi   = (const float*)d_in[1];
    const float* Re   = (const float*)d_in[2];
    const float* w1r  = (const float*)d_in[3];
    const float* w1i  = (const float*)d_in[4];
    const float* b1r  = (const float*)d_in[5];
    const float* b1i  = (const float*)d_in[6];
    const float* w2r  = (const float*)d_in[7];
    const float* w2i  = (const float*)d_in[8];
    const float* b2r  = (const float*)d_in[9];
    const float* b2i  = (const float*)d_in[10];
    const float* w0r  = (const float*)d_in[11];
    const float* w0i  = (const float*)d_in[12];
    const float* wd1r = (const float*)d_in[13];
    const float* wd1i = (const float*)d_in[14];
    const float* wu1r = (const float*)d_in[15];
    const float* wu1i = (const float*)d_in[16];
    const float* wd2r = (const float*)d_in[17];
    const float* wd2i = (const float*)d_in[18];
    const float* wu2r = (const float*)d_in[19];
    const float* wu2i = (const float*)d_in[20];

    float* out = (float*)d_out;

    k_prep  <<<51, 256>>>(Re, w1r, w1i, b1r, b1i);
    k_level0<<<2064, 256>>>(xr, xi, w2r, w2i, b2r, b2i, w0r, w0i, out);
    k_down1 <<<1024, 256>>>(wd1r, wd1i, out);
    k_mid   <<<1024, 128>>>(wd2r, wd2i, wu2r, wu2i, out);
    k_up1   <<<1024, 256>>>(wu1r, wu1i, out);
}